// round 3
// baseline (speedup 1.0000x reference)
#include <cuda_runtime.h>
#include <math.h>
#include <stdint.h>

// Problem dims
#define B_    262144
#define DIN   153
#define DOUT  8
#define NE    8
#define H1_   128
#define H2_   64
#define GH_   64
#define GH2_  32
#define EPS   1e-5f

#define MTILE 128
#define LDT   136   // padded row stride (floats) for transposed [K][128] smem tiles

// smem layout (floats)
#define OFF_XP   0
#define SZ_XP    (DIN*LDT)                 // x_proj^T  [153][136]
#define OFF_XS   (OFF_XP + SZ_XP)          // x_norm^T, later g1/h1
#define SZ_XS    (DIN*LDT)
#define OFF_G2   (OFF_XS + GH_*LDT)        // g2 inside XS region
#define OFF_H2   (OFF_XS + SZ_XS)          // h2^T [64][136]
#define SZ_H2    (H2_*LDT)
#define OFF_GATE (OFF_H2 + SZ_H2)          // gate^T [8][136]
#define SZ_GATE  (8*LDT)
#define OFF_ACC  (OFF_GATE + SZ_GATE)      // acc^T [8][136]
#define SZ_ACC   (8*LDT)
#define SMEM_FLOATS (OFF_ACC + SZ_ACC)     // 52496 floats = 209,984 B

// Generic tiled GEMM: O^T[N][128] = op(A^T[K][128] @ W[K][N] + bias)
// A in smem (transposed, stride LDT), W in global (L2-resident, tiny), O in smem.
// 256 threads = 16(tr) x 16(tc); thread does 8 rows x 1 col per 16-col chunk.
template<int K, int N, bool RELU, bool RESID>
__device__ __forceinline__ void gemmT(const float* __restrict__ As,
                                      const float* __restrict__ W,
                                      const float* __restrict__ bias,
                                      float* __restrict__ Ot,
                                      int tr, int tc)
{
    const int r0 = tr * 8;
    #pragma unroll 1
    for (int c0 = 0; c0 < N; c0 += 16) {
        const int col = c0 + tc;
        const bool ok = (col < N);
        const float* __restrict__ Wc = W + (ok ? col : (N - 1));
        float acc[8];
        #pragma unroll
        for (int i = 0; i < 8; i++) acc[i] = 0.f;
        #pragma unroll 8
        for (int k = 0; k < K; k++) {
            float4 a0 = *(const float4*)(As + k * LDT + r0);
            float4 a1 = *(const float4*)(As + k * LDT + r0 + 4);
            float w = Wc[(size_t)k * N];
            acc[0] = fmaf(a0.x, w, acc[0]);
            acc[1] = fmaf(a0.y, w, acc[1]);
            acc[2] = fmaf(a0.z, w, acc[2]);
            acc[3] = fmaf(a0.w, w, acc[3]);
            acc[4] = fmaf(a1.x, w, acc[4]);
            acc[5] = fmaf(a1.y, w, acc[5]);
            acc[6] = fmaf(a1.z, w, acc[6]);
            acc[7] = fmaf(a1.w, w, acc[7]);
        }
        if (ok) {
            const float b = bias[col];
            float* op = Ot + col * LDT + r0;
            #pragma unroll
            for (int i = 0; i < 8; i++) {
                float v = acc[i] + b;
                if (RELU) v = fmaxf(v, 0.f);
                if (RESID) v += As[col * LDT + r0 + i];
                op[i] = v;
            }
        }
    }
}

// Expert output GEMM (K=64, N=8) fused with gating-weighted accumulate:
// acc^T[o][r] += gate[r] * (h2^T @ We3 + be3)[o][r]
__device__ __forceinline__ void gemm_combine(const float* __restrict__ As,   // h2^T [64][136]
                                             const float* __restrict__ W,   // [64][8]
                                             const float* __restrict__ bias,// [8]
                                             const float* __restrict__ gate,// gate^T row for expert e: [136]
                                             float* __restrict__ accT,      // [8][136]
                                             int tr, int tc)
{
    if (tc >= 8) return;
    const int r0 = tr * 8;
    const int col = tc;
    float acc[8];
    #pragma unroll
    for (int i = 0; i < 8; i++) acc[i] = 0.f;
    #pragma unroll 8
    for (int k = 0; k < H2_; k++) {
        float4 a0 = *(const float4*)(As + k * LDT + r0);
        float4 a1 = *(const float4*)(As + k * LDT + r0 + 4);
        float w = W[k * 8 + col];
        acc[0] = fmaf(a0.x, w, acc[0]);
        acc[1] = fmaf(a0.y, w, acc[1]);
        acc[2] = fmaf(a0.z, w, acc[2]);
        acc[3] = fmaf(a0.w, w, acc[3]);
        acc[4] = fmaf(a1.x, w, acc[4]);
        acc[5] = fmaf(a1.y, w, acc[5]);
        acc[6] = fmaf(a1.z, w, acc[6]);
        acc[7] = fmaf(a1.w, w, acc[7]);
    }
    const float b = bias[col];
    float* ap = accT + col * LDT + r0;
    #pragma unroll
    for (int i = 0; i < 8; i++) {
        ap[i] += gate[r0 + i] * (acc[i] + b);
    }
}

__global__ __launch_bounds__(256, 1)
void moe_fused_kernel(const float* __restrict__ x,
                      const float* __restrict__ ln_in_g, const float* __restrict__ ln_in_b,
                      const float* __restrict__ Wp,  const float* __restrict__ bp,
                      const float* __restrict__ Wg1, const float* __restrict__ bg1,
                      const float* __restrict__ Wg2, const float* __restrict__ bg2,
                      const float* __restrict__ Wg3, const float* __restrict__ bg3,
                      const float* __restrict__ We1, const float* __restrict__ be1,
                      const float* __restrict__ We2, const float* __restrict__ be2,
                      const float* __restrict__ We3, const float* __restrict__ be3,
                      const float* __restrict__ ln_out_g, const float* __restrict__ ln_out_b,
                      float* __restrict__ out)
{
    extern __shared__ float sm[];
    const int tid = threadIdx.x;
    const int tr = tid >> 4, tc = tid & 15;
    const int row0 = blockIdx.x * MTILE;

    // zero the combine accumulator
    for (int i = tid; i < SZ_ACC; i += 256) sm[OFF_ACC + i] = 0.f;

    // ---- input LayerNorm: one warp per row, write x_norm^T ----
    {
        const int warp = tid >> 5, lane = tid & 31;
        for (int rr = warp; rr < MTILE; rr += 8) {
            const float* xr = x + (size_t)(row0 + rr) * DIN;
            float v[5];
            float s = 0.f, ss = 0.f;
            #pragma unroll
            for (int i = 0; i < 5; i++) {
                int k = i * 32 + lane;
                float val = (k < DIN) ? xr[k] : 0.f;
                v[i] = val; s += val; ss += val * val;
            }
            #pragma unroll
            for (int o = 16; o > 0; o >>= 1) {
                s  += __shfl_xor_sync(0xFFFFFFFFu, s,  o);
                ss += __shfl_xor_sync(0xFFFFFFFFu, ss, o);
            }
            const float m   = s * (1.f / DIN);
            const float var = ss * (1.f / DIN) - m * m;
            const float inv = rsqrtf(var + EPS);
            #pragma unroll
            for (int i = 0; i < 5; i++) {
                int k = i * 32 + lane;
                if (k < DIN)
                    sm[OFF_XS + k * LDT + rr] = (v[i] - m) * inv * ln_in_g[k] + ln_in_b[k];
            }
        }
    }
    __syncthreads();

    // ---- x_proj = relu(x_norm @ Wp + bp) + x_norm ----
    gemmT<DIN, DIN, true, true>(sm + OFF_XS, Wp, bp, sm + OFF_XP, tr, tc);
    __syncthreads();

    // ---- gating MLP ----
    gemmT<DIN, GH_, true, false>(sm + OFF_XP, Wg1, bg1, sm + OFF_XS, tr, tc);
    __syncthreads();
    gemmT<GH_, GH2_, true, false>(sm + OFF_XS, Wg2, bg2, sm + OFF_G2, tr, tc);
    __syncthreads();
    gemmT<GH2_, 8, false, false>(sm + OFF_G2, Wg3, bg3, sm + OFF_GATE, tr, tc);
    __syncthreads();

    // ---- softmax over experts, write gating output ----
    if (tid < MTILE) {
        float l[8];
        float mx = -INFINITY;
        #pragma unroll
        for (int e = 0; e < NE; e++) { l[e] = sm[OFF_GATE + e * LDT + tid]; mx = fmaxf(mx, l[e]); }
        float s = 0.f;
        #pragma unroll
        for (int e = 0; e < NE; e++) { l[e] = expf(l[e] - mx); s += l[e]; }
        const float invs = 1.f / s;
        float* gw = out + (size_t)B_ * 8 + (size_t)(row0 + tid) * 8;
        #pragma unroll
        for (int e = 0; e < NE; e++) {
            float g = l[e] * invs;
            sm[OFF_GATE + e * LDT + tid] = g;
            gw[e] = g;
        }
    }
    __syncthreads();

    // ---- experts: sequential, reuse smem ----
    for (int e = 0; e < NE; e++) {
        gemmT<DIN, H1_, true, false>(sm + OFF_XP, We1 + (size_t)e * DIN * H1_, be1 + e * H1_,
                                     sm + OFF_XS, tr, tc);
        __syncthreads();
        gemmT<H1_, H2_, true, false>(sm + OFF_XS, We2 + (size_t)e * H1_ * H2_, be2 + e * H2_,
                                     sm + OFF_H2, tr, tc);
        __syncthreads();
        gemm_combine(sm + OFF_H2, We3 + (size_t)e * H2_ * DOUT, be3 + e * DOUT,
                     sm + OFF_GATE + e * LDT, sm + OFF_ACC, tr, tc);
        __syncthreads();
    }

    // ---- output LayerNorm over 8 dims, write out ----
    if (tid < MTILE) {
        float y[8];
        float s = 0.f;
        #pragma unroll
        for (int e = 0; e < DOUT; e++) { y[e] = sm[OFF_ACC + e * LDT + tid]; s += y[e]; }
        const float m = s * 0.125f;
        float var = 0.f;
        #pragma unroll
        for (int e = 0; e < DOUT; e++) { float d = y[e] - m; var += d * d; }
        var *= 0.125f;
        const float inv = rsqrtf(var + EPS);
        float* op = out + (size_t)(row0 + tid) * 8;
        #pragma unroll
        for (int e = 0; e < DOUT; e++)
            op[e] = (y[e] - m) * inv * ln_out_g[e] + ln_out_b[e];
    }
}

extern "C" void kernel_launch(void* const* d_in, const int* in_sizes, int n_in,
                              void* d_out, int out_size)
{
    const float* x       = (const float*)d_in[0];
    const float* ln_in_g = (const float*)d_in[1];
    const float* ln_in_b = (const float*)d_in[2];
    const float* Wp      = (const float*)d_in[3];
    const float* bp      = (const float*)d_in[4];
    const float* Wg1     = (const float*)d_in[5];
    const float* bg1     = (const float*)d_in[6];
    const float* Wg2     = (const float*)d_in[7];
    const float* bg2     = (const float*)d_in[8];
    const float* Wg3     = (const float*)d_in[9];
    const float* bg3     = (const float*)d_in[10];
    const float* We1     = (const float*)d_in[11];
    const float* be1     = (const float*)d_in[12];
    const float* We2     = (const float*)d_in[13];
    const float* be2     = (const float*)d_in[14];
    const float* We3     = (const float*)d_in[15];
    const float* be3     = (const float*)d_in[16];
    const float* ln_out_g= (const float*)d_in[17];
    const float* ln_out_b= (const float*)d_in[18];
    float* out = (float*)d_out;

    const size_t smem = SMEM_FLOATS * sizeof(float);
    cudaFuncSetAttribute(moe_fused_kernel,
                         cudaFuncAttributeMaxDynamicSharedMemorySize, (int)smem);

    moe_fused_kernel<<<B_ / MTILE, 256, smem>>>(
        x, ln_in_g, ln_in_b, Wp, bp, Wg1, bg1, Wg2, bg2, Wg3, bg3,
        We1, be1, We2, be2, We3, be3, ln_out_g, ln_out_b, out);
}

// round 4
// speedup vs baseline: 1.4649x; 1.4649x over previous
#include <cuda_runtime.h>
#include <math.h>
#include <stdint.h>

// Problem dims
#define B_    262144
#define DIN   153
#define DOUT  8
#define NE    8
#define H1_   128
#define H2_   64
#define GH_   64
#define GH2_  32
#define EPS   1e-5f

#define MTILE 128
#define LDT   136   // padded row stride (floats) for transposed [K][128] smem tiles

// smem layout (floats)
#define OFF_XP   0
#define SZ_XP    (DIN*LDT)                 // x_proj^T  [153][136]
#define OFF_XS   (OFF_XP + SZ_XP)          // x_norm^T, later g1/h1
#define SZ_XS    (DIN*LDT)
#define OFF_G2   (OFF_XS + GH_*LDT)        // g2 inside XS region
#define OFF_H2   (OFF_XS + SZ_XS)          // h2^T [64][136]
#define SZ_H2    (H2_*LDT)
#define OFF_GATE (OFF_H2 + SZ_H2)          // gate^T [8][136]
#define SZ_GATE  (8*LDT)
#define OFF_ACC  (OFF_GATE + SZ_GATE)      // acc^T [8][136]
#define SZ_ACC   (8*LDT)
#define SMEM_FLOATS (OFF_ACC + SZ_ACC)     // 52496 floats = 209,984 B

// ---- packed f32x2 helpers (Blackwell FFMA2 path) ----
__device__ __forceinline__ uint64_t fma2(uint64_t a, uint64_t b, uint64_t c) {
    uint64_t d;
    asm("fma.rn.f32x2 %0, %1, %2, %3;" : "=l"(d) : "l"(a), "l"(b), "l"(c));
    return d;
}
__device__ __forceinline__ uint64_t add2(uint64_t a, uint64_t b) {
    uint64_t d;
    asm("add.rn.f32x2 %0, %1, %2;" : "=l"(d) : "l"(a), "l"(b));
    return d;
}
__device__ __forceinline__ uint64_t dup2(float w) {
    uint64_t d;
    asm("mov.b64 %0, {%1, %1};" : "=l"(d) : "f"(w));
    return d;
}
__device__ __forceinline__ void unpack2(uint64_t v, float& lo, float& hi) {
    asm("mov.b64 {%0, %1}, %2;" : "=f"(lo), "=f"(hi) : "l"(v));
}

// Tiled GEMM: O^T[N][128] = op(A^T[K][128] @ W[K][N] + bias)
// 256 threads = 16(tr) x 16(tc); thread computes 8 rows (as 4 f32x2) x up to 4 cols.
template<int K, int N, bool RELU, bool RESID>
__device__ __forceinline__ void gemmT(const float* __restrict__ As,
                                      const float* __restrict__ W,
                                      const float* __restrict__ bias,
                                      float* __restrict__ Ot,
                                      int tr, int tc)
{
    const int r0 = tr * 8;
    #pragma unroll
    for (int c0 = 0; c0 < N; c0 += 64) {
        uint64_t acc[4][4];
        #pragma unroll
        for (int j = 0; j < 4; j++)
            #pragma unroll
            for (int q = 0; q < 4; q++) acc[j][q] = 0ull;

        const float* __restrict__ Wc[4];
        bool ok[4];
        #pragma unroll
        for (int j = 0; j < 4; j++) {
            if (c0 + 16 * j < N) {          // compile-time prune of whole group
                int col = c0 + 16 * j + tc;
                ok[j] = (col < N);
                Wc[j] = W + (ok[j] ? col : 0);
            }
        }

        #pragma unroll 4
        for (int k = 0; k < K; k++) {
            const float* ap = As + k * LDT + r0;
            ulonglong2 A0 = *(const ulonglong2*)(ap);
            ulonglong2 A1 = *(const ulonglong2*)(ap + 4);
            #pragma unroll
            for (int j = 0; j < 4; j++) {
                if (c0 + 16 * j < N) {
                    uint64_t wd = dup2(Wc[j][(size_t)k * N]);
                    acc[j][0] = fma2(A0.x, wd, acc[j][0]);
                    acc[j][1] = fma2(A0.y, wd, acc[j][1]);
                    acc[j][2] = fma2(A1.x, wd, acc[j][2]);
                    acc[j][3] = fma2(A1.y, wd, acc[j][3]);
                }
            }
        }

        #pragma unroll
        for (int j = 0; j < 4; j++) {
            if (c0 + 16 * j < N) {
                int col = c0 + 16 * j + tc;
                if (ok[j]) {
                    const float b = bias[col];
                    float* op = Ot + col * LDT + r0;
                    #pragma unroll
                    for (int q = 0; q < 4; q++) {
                        float lo, hi;
                        unpack2(acc[j][q], lo, hi);
                        float v0 = lo + b, v1 = hi + b;
                        if (RELU) { v0 = fmaxf(v0, 0.f); v1 = fmaxf(v1, 0.f); }
                        if (RESID) {
                            v0 += As[col * LDT + r0 + 2 * q];
                            v1 += As[col * LDT + r0 + 2 * q + 1];
                        }
                        op[2 * q]     = v0;
                        op[2 * q + 1] = v1;
                    }
                }
            }
        }
    }
}

// Expert output GEMM (K=64, N=8) fused with gating-weighted accumulate.
// All 256 threads: col = tc&7, k-half = tc>>3; partner partials merged by shfl.
__device__ __forceinline__ void gemm_combine(const float* __restrict__ As,   // h2^T [64][136]
                                             const float* __restrict__ W,   // [64][8]
                                             const float* __restrict__ bias,// [8]
                                             const float* __restrict__ gate,// gate row for expert e
                                             float* __restrict__ accT,      // [8][136]
                                             int tr, int tc)
{
    const int r0  = tr * 8;
    const int col = tc & 7;
    const int k0  = (tc >> 3) * 32;
    uint64_t acc[4] = {0ull, 0ull, 0ull, 0ull};
    const float* __restrict__ Wc = W + k0 * 8 + col;
    #pragma unroll 4
    for (int k = 0; k < 32; k++) {
        const float* ap = As + (k0 + k) * LDT + r0;
        ulonglong2 A0 = *(const ulonglong2*)(ap);
        ulonglong2 A1 = *(const ulonglong2*)(ap + 4);
        uint64_t wd = dup2(Wc[k * 8]);
        acc[0] = fma2(A0.x, wd, acc[0]);
        acc[1] = fma2(A0.y, wd, acc[1]);
        acc[2] = fma2(A1.x, wd, acc[2]);
        acc[3] = fma2(A1.y, wd, acc[3]);
    }
    // merge k-half partial from lane+8 (same tr, tc+8) into tc<8 lanes
    #pragma unroll
    for (int q = 0; q < 4; q++) {
        double other = __shfl_down_sync(0xFFFFFFFFu,
                                        __longlong_as_double((long long)acc[q]), 8);
        acc[q] = add2(acc[q], (uint64_t)__double_as_longlong(other));
    }
    if (tc < 8) {
        const float b = bias[col];
        float* ap = accT + col * LDT + r0;
        #pragma unroll
        for (int q = 0; q < 4; q++) {
            float lo, hi;
            unpack2(acc[q], lo, hi);
            ap[2 * q]     += gate[r0 + 2 * q]     * (lo + b);
            ap[2 * q + 1] += gate[r0 + 2 * q + 1] * (hi + b);
        }
    }
}

__global__ __launch_bounds__(256, 1)
void moe_fused_kernel(const float* __restrict__ x,
                      const float* __restrict__ ln_in_g, const float* __restrict__ ln_in_b,
                      const float* __restrict__ Wp,  const float* __restrict__ bp,
                      const float* __restrict__ Wg1, const float* __restrict__ bg1,
                      const float* __restrict__ Wg2, const float* __restrict__ bg2,
                      const float* __restrict__ Wg3, const float* __restrict__ bg3,
                      const float* __restrict__ We1, const float* __restrict__ be1,
                      const float* __restrict__ We2, const float* __restrict__ be2,
                      const float* __restrict__ We3, const float* __restrict__ be3,
                      const float* __restrict__ ln_out_g, const float* __restrict__ ln_out_b,
                      float* __restrict__ out)
{
    extern __shared__ float sm[];
    const int tid = threadIdx.x;
    const int tr = tid >> 4, tc = tid & 15;
    const int row0 = blockIdx.x * MTILE;

    // zero the combine accumulator
    for (int i = tid; i < SZ_ACC; i += 256) sm[OFF_ACC + i] = 0.f;

    // ---- input LayerNorm: one warp per row, write x_norm^T ----
    {
        const int warp = tid >> 5, lane = tid & 31;
        for (int rr = warp; rr < MTILE; rr += 8) {
            const float* xr = x + (size_t)(row0 + rr) * DIN;
            float v[5];
            float s = 0.f, ss = 0.f;
            #pragma unroll
            for (int i = 0; i < 5; i++) {
                int k = i * 32 + lane;
                float val = (k < DIN) ? xr[k] : 0.f;
                v[i] = val; s += val; ss += val * val;
            }
            #pragma unroll
            for (int o = 16; o > 0; o >>= 1) {
                s  += __shfl_xor_sync(0xFFFFFFFFu, s,  o);
                ss += __shfl_xor_sync(0xFFFFFFFFu, ss, o);
            }
            const float m   = s * (1.f / DIN);
            const float var = ss * (1.f / DIN) - m * m;
            const float inv = rsqrtf(var + EPS);
            #pragma unroll
            for (int i = 0; i < 5; i++) {
                int k = i * 32 + lane;
                if (k < DIN)
                    sm[OFF_XS + k * LDT + rr] = (v[i] - m) * inv * ln_in_g[k] + ln_in_b[k];
            }
        }
    }
    __syncthreads();

    // ---- x_proj = relu(x_norm @ Wp + bp) + x_norm ----
    gemmT<DIN, DIN, true, true>(sm + OFF_XS, Wp, bp, sm + OFF_XP, tr, tc);
    __syncthreads();

    // ---- gating MLP ----
    gemmT<DIN, GH_, true, false>(sm + OFF_XP, Wg1, bg1, sm + OFF_XS, tr, tc);
    __syncthreads();
    gemmT<GH_, GH2_, true, false>(sm + OFF_XS, Wg2, bg2, sm + OFF_G2, tr, tc);
    __syncthreads();
    gemmT<GH2_, 8, false, false>(sm + OFF_G2, Wg3, bg3, sm + OFF_GATE, tr, tc);
    __syncthreads();

    // ---- softmax over experts, write gating output ----
    if (tid < MTILE) {
        float l[8];
        float mx = -INFINITY;
        #pragma unroll
        for (int e = 0; e < NE; e++) { l[e] = sm[OFF_GATE + e * LDT + tid]; mx = fmaxf(mx, l[e]); }
        float s = 0.f;
        #pragma unroll
        for (int e = 0; e < NE; e++) { l[e] = expf(l[e] - mx); s += l[e]; }
        const float invs = 1.f / s;
        float* gw = out + (size_t)B_ * 8 + (size_t)(row0 + tid) * 8;
        #pragma unroll
        for (int e = 0; e < NE; e++) {
            float g = l[e] * invs;
            sm[OFF_GATE + e * LDT + tid] = g;
            gw[e] = g;
        }
    }
    __syncthreads();

    // ---- experts: sequential, reuse smem ----
    for (int e = 0; e < NE; e++) {
        gemmT<DIN, H1_, true, false>(sm + OFF_XP, We1 + (size_t)e * DIN * H1_, be1 + e * H1_,
                                     sm + OFF_XS, tr, tc);
        __syncthreads();
        gemmT<H1_, H2_, true, false>(sm + OFF_XS, We2 + (size_t)e * H1_ * H2_, be2 + e * H2_,
                                     sm + OFF_H2, tr, tc);
        __syncthreads();
        gemm_combine(sm + OFF_H2, We3 + (size_t)e * H2_ * DOUT, be3 + e * DOUT,
                     sm + OFF_GATE + e * LDT, sm + OFF_ACC, tr, tc);
        // no barrier needed: combine touches H2/GATE/ACC; next We1 gemm writes XS only,
        // and the barrier after We1 orders it before We2's H2 writes.
    }
    __syncthreads();

    // ---- output LayerNorm over 8 dims, write out ----
    if (tid < MTILE) {
        float y[8];
        float s = 0.f;
        #pragma unroll
        for (int e = 0; e < DOUT; e++) { y[e] = sm[OFF_ACC + e * LDT + tid]; s += y[e]; }
        const float m = s * 0.125f;
        float var = 0.f;
        #pragma unroll
        for (int e = 0; e < DOUT; e++) { float d = y[e] - m; var += d * d; }
        var *= 0.125f;
        const float inv = rsqrtf(var + EPS);
        float* op = out + (size_t)(row0 + tid) * 8;
        #pragma unroll
        for (int e = 0; e < DOUT; e++)
            op[e] = (y[e] - m) * inv * ln_out_g[e] + ln_out_b[e];
    }
}

extern "C" void kernel_launch(void* const* d_in, const int* in_sizes, int n_in,
                              void* d_out, int out_size)
{
    const float* x       = (const float*)d_in[0];
    const float* ln_in_g = (const float*)d_in[1];
    const float* ln_in_b = (const float*)d_in[2];
    const float* Wp      = (const float*)d_in[3];
    const float* bp      = (const float*)d_in[4];
    const float* Wg1     = (const float*)d_in[5];
    const float* bg1     = (const float*)d_in[6];
    const float* Wg2     = (const float*)d_in[7];
    const float* bg2     = (const float*)d_in[8];
    const float* Wg3     = (const float*)d_in[9];
    const float* bg3     = (const float*)d_in[10];
    const float* We1     = (const float*)d_in[11];
    const float* be1     = (const float*)d_in[12];
    const float* We2     = (const float*)d_in[13];
    const float* be2     = (const float*)d_in[14];
    const float* We3     = (const float*)d_in[15];
    const float* be3     = (const float*)d_in[16];
    const float* ln_out_g= (const float*)d_in[17];
    const float* ln_out_b= (const float*)d_in[18];
    float* out = (float*)d_out;

    const size_t smem = SMEM_FLOATS * sizeof(float);
    cudaFuncSetAttribute(moe_fused_kernel,
                         cudaFuncAttributeMaxDynamicSharedMemorySize, (int)smem);

    moe_fused_kernel<<<B_ / MTILE, 256, smem>>>(
        x, ln_in_g, ln_in_b, Wp, bp, Wg1, bg1, Wg2, bg2, Wg3, bg3,
        We1, be1, We2, be2, We3, be3, ln_out_g, ln_out_b, out);
}

// round 5
// speedup vs baseline: 2.1570x; 1.4724x over previous
#include <cuda_runtime.h>
#include <math.h>
#include <stdint.h>

// Problem dims
#define B_    262144
#define DIN   153
#define DOUT  8
#define NE    8
#define H1_   128
#define H2_   64
#define GH_   64
#define GH2_  32
#define EPS   1e-5f

#define MTILE 128
#define NTHREADS 512
#define LDT   136   // padded row stride (floats) for transposed [K][128] smem tiles

// smem layout (floats)
#define OFF_XP   0
#define SZ_XP    (DIN*LDT)                 // x_proj^T  [153][136]
#define OFF_XS   (OFF_XP + SZ_XP)          // x_norm^T, later g1/h1
#define SZ_XS    (DIN*LDT)
#define OFF_G2   (OFF_XS + GH_*LDT)        // g2 inside XS region
#define OFF_H2   (OFF_XS + SZ_XS)          // h2^T [64][136]
#define SZ_H2    (H2_*LDT)
#define OFF_GATE (OFF_H2 + SZ_H2)          // gate^T [8][136]
#define SZ_GATE  (8*LDT)
#define OFF_ACC  (OFF_GATE + SZ_GATE)      // acc^T [8][136]
#define SZ_ACC   (8*LDT)
#define SMEM_FLOATS (OFF_ACC + SZ_ACC)     // 52496 floats = 209,984 B

// ---- packed f32x2 helpers (Blackwell FFMA2 path) ----
__device__ __forceinline__ uint64_t fma2(uint64_t a, uint64_t b, uint64_t c) {
    uint64_t d;
    asm("fma.rn.f32x2 %0, %1, %2, %3;" : "=l"(d) : "l"(a), "l"(b), "l"(c));
    return d;
}
__device__ __forceinline__ uint64_t add2(uint64_t a, uint64_t b) {
    uint64_t d;
    asm("add.rn.f32x2 %0, %1, %2;" : "=l"(d) : "l"(a), "l"(b));
    return d;
}
__device__ __forceinline__ uint64_t dup2(float w) {
    uint64_t d;
    asm("mov.b64 %0, {%1, %1};" : "=l"(d) : "f"(w));
    return d;
}
__device__ __forceinline__ void unpack2(uint64_t v, float& lo, float& hi) {
    asm("mov.b64 {%0, %1}, %2;" : "=f"(lo), "=f"(hi) : "l"(v));
}

// Tiled GEMM: O^T[N][128] = op(A^T[K][128] @ W[K][N] + bias)
// 512 threads = 16(tr) x 32(tc); thread computes 8 rows (4 f32x2) x up to 4 cols
// (column groups at stride 32 within a 128-column block).
template<int K, int N, bool RELU, bool RESID>
__device__ __forceinline__ void gemmT(const float* __restrict__ As,
                                      const float* __restrict__ W,
                                      const float* __restrict__ bias,
                                      float* __restrict__ Ot,
                                      int tr, int tc)
{
    const int r0 = tr * 8;
    #pragma unroll
    for (int c0 = 0; c0 < N; c0 += 128) {
        uint64_t acc[4][4];
        #pragma unroll
        for (int j = 0; j < 4; j++)
            #pragma unroll
            for (int q = 0; q < 4; q++) acc[j][q] = 0ull;

        const float* __restrict__ Wc[4];
        bool ok[4];
        #pragma unroll
        for (int j = 0; j < 4; j++) {
            if (c0 + 32 * j < N) {          // compile-time prune of whole group
                int col = c0 + 32 * j + tc;
                ok[j] = (col < N);
                Wc[j] = W + (ok[j] ? col : 0);
            }
        }

        #pragma unroll 4
        for (int k = 0; k < K; k++) {
            const float* ap = As + k * LDT + r0;
            ulonglong2 A0 = *(const ulonglong2*)(ap);
            ulonglong2 A1 = *(const ulonglong2*)(ap + 4);
            #pragma unroll
            for (int j = 0; j < 4; j++) {
                if (c0 + 32 * j < N) {
                    uint64_t wd = dup2(Wc[j][(size_t)k * N]);
                    acc[j][0] = fma2(A0.x, wd, acc[j][0]);
                    acc[j][1] = fma2(A0.y, wd, acc[j][1]);
                    acc[j][2] = fma2(A1.x, wd, acc[j][2]);
                    acc[j][3] = fma2(A1.y, wd, acc[j][3]);
                }
            }
        }

        #pragma unroll
        for (int j = 0; j < 4; j++) {
            if (c0 + 32 * j < N) {
                int col = c0 + 32 * j + tc;
                if (ok[j]) {
                    const float b = bias[col];
                    float* op = Ot + col * LDT + r0;
                    #pragma unroll
                    for (int q = 0; q < 4; q++) {
                        float lo, hi;
                        unpack2(acc[j][q], lo, hi);
                        float v0 = lo + b, v1 = hi + b;
                        if (RELU) { v0 = fmaxf(v0, 0.f); v1 = fmaxf(v1, 0.f); }
                        if (RESID) {
                            v0 += As[col * LDT + r0 + 2 * q];
                            v1 += As[col * LDT + r0 + 2 * q + 1];
                        }
                        op[2 * q]     = v0;
                        op[2 * q + 1] = v1;
                    }
                }
            }
        }
    }
}

// Expert output GEMM (K=64, N=8) fused with gating-weighted accumulate.
// 512 threads: col = tc&7, k-quarter = tc>>3 (16 k's each); shuffle-tree merge.
__device__ __forceinline__ void gemm_combine(const float* __restrict__ As,   // h2^T [64][136]
                                             const float* __restrict__ W,   // [64][8]
                                             const float* __restrict__ bias,// [8]
                                             const float* __restrict__ gate,// gate row for expert e
                                             float* __restrict__ accT,      // [8][136]
                                             int tr, int tc)
{
    const int r0  = tr * 8;
    const int col = tc & 7;
    const int k0  = (tc >> 3) * 16;
    uint64_t acc[4] = {0ull, 0ull, 0ull, 0ull};
    const float* __restrict__ Wc = W + k0 * 8 + col;
    #pragma unroll 4
    for (int k = 0; k < 16; k++) {
        const float* ap = As + (k0 + k) * LDT + r0;
        ulonglong2 A0 = *(const ulonglong2*)(ap);
        ulonglong2 A1 = *(const ulonglong2*)(ap + 4);
        uint64_t wd = dup2(Wc[k * 8]);
        acc[0] = fma2(A0.x, wd, acc[0]);
        acc[1] = fma2(A0.y, wd, acc[1]);
        acc[2] = fma2(A1.x, wd, acc[2]);
        acc[3] = fma2(A1.y, wd, acc[3]);
    }
    // merge the 4 k-quarters (lanes l, l+8, l+16, l+24)
    #pragma unroll
    for (int q = 0; q < 4; q++) {
        double o16 = __shfl_down_sync(0xFFFFFFFFu,
                                      __longlong_as_double((long long)acc[q]), 16);
        acc[q] = add2(acc[q], (uint64_t)__double_as_longlong(o16));
        double o8 = __shfl_down_sync(0xFFFFFFFFu,
                                     __longlong_as_double((long long)acc[q]), 8);
        acc[q] = add2(acc[q], (uint64_t)__double_as_longlong(o8));
    }
    if (tc < 8) {
        const float b = bias[col];
        float* ap = accT + col * LDT + r0;
        #pragma unroll
        for (int q = 0; q < 4; q++) {
            float lo, hi;
            unpack2(acc[q], lo, hi);
            ap[2 * q]     += gate[r0 + 2 * q]     * (lo + b);
            ap[2 * q + 1] += gate[r0 + 2 * q + 1] * (hi + b);
        }
    }
}

__global__ __launch_bounds__(NTHREADS, 1)
void moe_fused_kernel(const float* __restrict__ x,
                      const float* __restrict__ ln_in_g, const float* __restrict__ ln_in_b,
                      const float* __restrict__ Wp,  const float* __restrict__ bp,
                      const float* __restrict__ Wg1, const float* __restrict__ bg1,
                      const float* __restrict__ Wg2, const float* __restrict__ bg2,
                      const float* __restrict__ Wg3, const float* __restrict__ bg3,
                      const float* __restrict__ We1, const float* __restrict__ be1,
                      const float* __restrict__ We2, const float* __restrict__ be2,
                      const float* __restrict__ We3, const float* __restrict__ be3,
                      const float* __restrict__ ln_out_g, const float* __restrict__ ln_out_b,
                      float* __restrict__ out)
{
    extern __shared__ float sm[];
    const int tid = threadIdx.x;
    const int tr = tid >> 5, tc = tid & 31;
    const int row0 = blockIdx.x * MTILE;

    // zero the combine accumulator
    for (int i = tid; i < SZ_ACC; i += NTHREADS) sm[OFF_ACC + i] = 0.f;

    // ---- input LayerNorm: one warp per row, write x_norm^T ----
    {
        const int warp = tid >> 5, lane = tid & 31;
        for (int rr = warp; rr < MTILE; rr += 16) {
            const float* xr = x + (size_t)(row0 + rr) * DIN;
            float v[5];
            float s = 0.f, ss = 0.f;
            #pragma unroll
            for (int i = 0; i < 5; i++) {
                int k = i * 32 + lane;
                float val = (k < DIN) ? xr[k] : 0.f;
                v[i] = val; s += val; ss += val * val;
            }
            #pragma unroll
            for (int o = 16; o > 0; o >>= 1) {
                s  += __shfl_xor_sync(0xFFFFFFFFu, s,  o);
                ss += __shfl_xor_sync(0xFFFFFFFFu, ss, o);
            }
            const float m   = s * (1.f / DIN);
            const float var = ss * (1.f / DIN) - m * m;
            const float inv = rsqrtf(var + EPS);
            #pragma unroll
            for (int i = 0; i < 5; i++) {
                int k = i * 32 + lane;
                if (k < DIN)
                    sm[OFF_XS + k * LDT + rr] = (v[i] - m) * inv * ln_in_g[k] + ln_in_b[k];
            }
        }
    }
    __syncthreads();

    // ---- x_proj = relu(x_norm @ Wp + bp) + x_norm ----
    gemmT<DIN, DIN, true, true>(sm + OFF_XS, Wp, bp, sm + OFF_XP, tr, tc);
    __syncthreads();

    // ---- gating MLP ----
    gemmT<DIN, GH_, true, false>(sm + OFF_XP, Wg1, bg1, sm + OFF_XS, tr, tc);
    __syncthreads();
    gemmT<GH_, GH2_, true, false>(sm + OFF_XS, Wg2, bg2, sm + OFF_G2, tr, tc);
    __syncthreads();
    gemmT<GH2_, 8, false, false>(sm + OFF_G2, Wg3, bg3, sm + OFF_GATE, tr, tc);
    __syncthreads();

    // ---- softmax over experts, write gating output ----
    if (tid < MTILE) {
        float l[8];
        float mx = -INFINITY;
        #pragma unroll
        for (int e = 0; e < NE; e++) { l[e] = sm[OFF_GATE + e * LDT + tid]; mx = fmaxf(mx, l[e]); }
        float s = 0.f;
        #pragma unroll
        for (int e = 0; e < NE; e++) { l[e] = expf(l[e] - mx); s += l[e]; }
        const float invs = 1.f / s;
        float* gw = out + (size_t)B_ * 8 + (size_t)(row0 + tid) * 8;
        #pragma unroll
        for (int e = 0; e < NE; e++) {
            float g = l[e] * invs;
            sm[OFF_GATE + e * LDT + tid] = g;
            gw[e] = g;
        }
    }
    __syncthreads();

    // ---- experts: sequential, reuse smem ----
    for (int e = 0; e < NE; e++) {
        gemmT<DIN, H1_, true, false>(sm + OFF_XP, We1 + (size_t)e * DIN * H1_, be1 + e * H1_,
                                     sm + OFF_XS, tr, tc);
        __syncthreads();
        gemmT<H1_, H2_, true, false>(sm + OFF_XS, We2 + (size_t)e * H1_ * H2_, be2 + e * H2_,
                                     sm + OFF_H2, tr, tc);
        __syncthreads();
        gemm_combine(sm + OFF_H2, We3 + (size_t)e * H2_ * DOUT, be3 + e * DOUT,
                     sm + OFF_GATE + e * LDT, sm + OFF_ACC, tr, tc);
        // no barrier needed: combine reads H2/GATE, writes ACC; next We1 gemm
        // writes XS only, and the barrier after it orders everything else.
    }
    __syncthreads();

    // ---- output LayerNorm over 8 dims, write out ----
    if (tid < MTILE) {
        float y[8];
        float s = 0.f;
        #pragma unroll
        for (int e = 0; e < DOUT; e++) { y[e] = sm[OFF_ACC + e * LDT + tid]; s += y[e]; }
        const float m = s * 0.125f;
        float var = 0.f;
        #pragma unroll
        for (int e = 0; e < DOUT; e++) { float d = y[e] - m; var += d * d; }
        var *= 0.125f;
        const float inv = rsqrtf(var + EPS);
        float* op = out + (size_t)(row0 + tid) * 8;
        #pragma unroll
        for (int e = 0; e < DOUT; e++)
            op[e] = (y[e] - m) * inv * ln_out_g[e] + ln_out_b[e];
    }
}

extern "C" void kernel_launch(void* const* d_in, const int* in_sizes, int n_in,
                              void* d_out, int out_size)
{
    const float* x       = (const float*)d_in[0];
    const float* ln_in_g = (const float*)d_in[1];
    const float* ln_in_b = (const float*)d_in[2];
    const float* Wp      = (const float*)d_in[3];
    const float* bp      = (const float*)d_in[4];
    const float* Wg1     = (const float*)d_in[5];
    const float* bg1     = (const float*)d_in[6];
    const float* Wg2     = (const float*)d_in[7];
    const float* bg2     = (const float*)d_in[8];
    const float* Wg3     = (const float*)d_in[9];
    const float* bg3     = (const float*)d_in[10];
    const float* We1     = (const float*)d_in[11];
    const float* be1     = (const float*)d_in[12];
    const float* We2     = (const float*)d_in[13];
    const float* be2     = (const float*)d_in[14];
    const float* We3     = (const float*)d_in[15];
    const float* be3     = (const float*)d_in[16];
    const float* ln_out_g= (const float*)d_in[17];
    const float* ln_out_b= (const float*)d_in[18];
    float* out = (float*)d_out;

    const size_t smem = SMEM_FLOATS * sizeof(float);
    cudaFuncSetAttribute(moe_fused_kernel,
                         cudaFuncAttributeMaxDynamicSharedMemorySize, (int)smem);

    moe_fused_kernel<<<B_ / MTILE, NTHREADS, smem>>>(
        x, ln_in_g, ln_in_b, Wp, bp, Wg1, bg1, Wg2, bg2, Wg3, bg3,
        We1, be1, We2, be2, We3, be3, ln_out_g, ln_out_b, out);
}

// round 7
// speedup vs baseline: 2.9192x; 1.3534x over previous
#include <cuda_runtime.h>
#include <math.h>
#include <stdint.h>

// Problem dims
#define B_    262144
#define DIN   153
#define DOUT  8
#define NE    8
#define H1_   128
#define H2_   64
#define GH_   64
#define GH2_  32
#define EPS   1e-5f

#define MTILE 128
#define NTHREADS 512
#define LDT   136    // padded row stride (floats) for transposed [K][128] smem tiles
#define KPAD  160    // padded K rows (DIN=153 -> 160) for mma A tiles

// smem layout (floats)
#define OFF_XP   0
#define SZ_XP    (KPAD*LDT)                // x_proj^T  [160][136] (rows 153..159 zero)
#define OFF_XS   (OFF_XP + SZ_XP)          // x_norm^T / g1 / h1   [160][136]
#define SZ_XS    (KPAD*LDT)
#define OFF_G2   (OFF_XS + GH_*LDT)        // g2 inside XS region (rows 64..95)
#define OFF_H2   (OFF_XS + SZ_XS)          // h2^T [64][136]
#define SZ_H2    (H2_*LDT)
#define OFF_GATE (OFF_H2 + SZ_H2)          // gate^T [8][136]
#define SZ_GATE  (8*LDT)
#define OFF_ACC  (OFF_GATE + SZ_GATE)      // acc^T [8][136]
#define SZ_ACC   (8*LDT)
#define SMEM_FLOATS (OFF_ACC + SZ_ACC)     // 54400 floats = 217,600 B

// ---- packed f32x2 helpers (FFMA2 path for gating/combine) ----
__device__ __forceinline__ uint64_t fma2(uint64_t a, uint64_t b, uint64_t c) {
    uint64_t d;
    asm("fma.rn.f32x2 %0, %1, %2, %3;" : "=l"(d) : "l"(a), "l"(b), "l"(c));
    return d;
}
__device__ __forceinline__ uint64_t add2(uint64_t a, uint64_t b) {
    uint64_t d;
    asm("add.rn.f32x2 %0, %1, %2;" : "=l"(d) : "l"(a), "l"(b));
    return d;
}
__device__ __forceinline__ uint64_t dup2(float w) {
    uint64_t d;
    asm("mov.b64 %0, {%1, %1};" : "=l"(d) : "f"(w));
    return d;
}
__device__ __forceinline__ void unpack2(uint64_t v, float& lo, float& hi) {
    asm("mov.b64 {%0, %1}, %2;" : "=f"(lo), "=f"(hi) : "l"(v));
}

// tf32 round-to-nearest (keeps value in a f32 register with low mantissa zeroed)
__device__ __forceinline__ float tf32r(float x) {
    uint32_t u;
    asm("cvt.rna.tf32.f32 %0, %1;" : "=r"(u) : "f"(x));
    return __uint_as_float(u);
}

// ---- warp-level tf32 MMA m16n8k8 ----
__device__ __forceinline__ void mma8(float* d,
                                     uint32_t a0, uint32_t a1, uint32_t a2, uint32_t a3,
                                     uint32_t b0, uint32_t b1) {
    asm volatile(
        "mma.sync.aligned.m16n8k8.row.col.f32.tf32.tf32.f32 "
        "{%0,%1,%2,%3},{%4,%5,%6,%7},{%8,%9},{%0,%1,%2,%3};"
        : "+f"(d[0]), "+f"(d[1]), "+f"(d[2]), "+f"(d[3])
        : "r"(a0), "r"(a1), "r"(a2), "r"(a3), "r"(b0), "r"(b1));
}

// Tensor-core GEMM: O^T[N][128] = op(A^T[Kpad][128] @ W[K][N] + bias)
// 16 warps: row-group = warp&7 (16 rows each), col-group = warp>>3 (n-tiles stride 2).
// A in smem transposed (stride LDT, rows 0..ceil8(K)-1 valid, pad rows zero).
// W in global [K][N]. Output written tf32-rounded if TF32OUT.
template<int K, int N, bool RELU, bool RESID, bool TF32OUT>
__device__ __forceinline__ void mma_gemmT(const float* __restrict__ As,
                                          const float* __restrict__ W,
                                          const float* __restrict__ bias,
                                          float* __restrict__ Ot,
                                          int warp, int lane)
{
    constexpr int KT  = K / 8;            // full k-steps
    constexpr int KR  = K % 8;            // tail
    constexpr int NT  = (N + 7) / 8;      // n-tiles (even in all our cases)
    constexpr int NTW = (NT + 1) / 2;     // n-tiles per col-group

    const int row0 = (warp & 7) * 16;
    const int colg = warp >> 3;           // 0 or 1
    const int gid  = lane >> 2;
    const int tig  = lane & 3;
    const int r_lo = row0 + gid;
    const int r_hi = row0 + gid + 8;

    float acc[NTW][4];
    #pragma unroll
    for (int i = 0; i < NTW; i++)
        #pragma unroll
        for (int q = 0; q < 4; q++) acc[i][q] = 0.f;

    #pragma unroll 2
    for (int ks = 0; ks < KT; ks++) {
        const int k0 = ks * 8;
        const float* ap0 = As + (k0 + tig) * LDT;
        const float* ap1 = ap0 + 4 * LDT;
        uint32_t a0 = __float_as_uint(ap0[r_lo]);
        uint32_t a1 = __float_as_uint(ap0[r_hi]);
        uint32_t a2 = __float_as_uint(ap1[r_lo]);
        uint32_t a3 = __float_as_uint(ap1[r_hi]);
        const float* wr0 = W + (size_t)(k0 + tig) * N;
        const float* wr1 = wr0 + (size_t)4 * N;
        #pragma unroll
        for (int i = 0; i < NTW; i++) {
            const int nt  = colg + 2 * i;
            const int col = nt * 8 + gid;
            uint32_t b0 = 0, b1 = 0;
            if ((N % 8 == 0) || (nt != NT - 1) || (col < N)) {
                b0 = __float_as_uint(wr0[col]);
                b1 = __float_as_uint(wr1[col]);
            }
            mma8(acc[i], a0, a1, a2, a3, b0, b1);
        }
    }
    if (KR) {   // guarded tail k-step (A pad rows are zero; W guarded)
        const int k0 = KT * 8;
        const float* ap0 = As + (k0 + tig) * LDT;
        const float* ap1 = ap0 + 4 * LDT;
        uint32_t a0 = __float_as_uint(ap0[r_lo]);
        uint32_t a1 = __float_as_uint(ap0[r_hi]);
        uint32_t a2 = __float_as_uint(ap1[r_lo]);
        uint32_t a3 = __float_as_uint(ap1[r_hi]);
        const bool kv0 = (tig < KR);
        const bool kv1 = (tig + 4 < KR);
        #pragma unroll
        for (int i = 0; i < NTW; i++) {
            const int nt  = colg + 2 * i;
            const int col = nt * 8 + gid;
            const bool nv = (N % 8 == 0) || (nt != NT - 1) || (col < N);
            uint32_t b0 = 0, b1 = 0;
            if (kv0 && nv) b0 = __float_as_uint(W[(size_t)(k0 + tig) * N + col]);
            if (kv1 && nv) b1 = __float_as_uint(W[(size_t)(k0 + tig + 4) * N + col]);
            mma8(acc[i], a0, a1, a2, a3, b0, b1);
        }
    }

    // epilogue
    #pragma unroll
    for (int i = 0; i < NTW; i++) {
        const int nt = colg + 2 * i;
        #pragma unroll
        for (int h = 0; h < 2; h++) {
            const int col = nt * 8 + tig * 2 + h;
            if ((N % 8 == 0) || (nt != NT - 1) || (col < N)) {
                const float b = bias[col];
                float v_lo = acc[i][h]     + b;
                float v_hi = acc[i][2 + h] + b;
                if (RELU) { v_lo = fmaxf(v_lo, 0.f); v_hi = fmaxf(v_hi, 0.f); }
                if (RESID) {
                    v_lo += As[col * LDT + r_lo];
                    v_hi += As[col * LDT + r_hi];
                }
                if (TF32OUT) { v_lo = tf32r(v_lo); v_hi = tf32r(v_hi); }
                Ot[col * LDT + r_lo] = v_lo;
                Ot[col * LDT + r_hi] = v_hi;
            }
        }
    }
}

// Scalar FFMA2 GEMM (gating path, fp32): O^T[N][128] = op(A^T @ W + bias)
// 512 threads = 16(tr) x 32(tc); 8 rows (4 f32x2) x up to 4 cols (stride 32).
template<int K, int N, bool RELU>
__device__ __forceinline__ void gemmT(const float* __restrict__ As,
                                      const float* __restrict__ W,
                                      const float* __restrict__ bias,
                                      float* __restrict__ Ot,
                                      int tr, int tc)
{
    const int r0 = tr * 8;
    uint64_t acc[4][4];
    #pragma unroll
    for (int j = 0; j < 4; j++)
        #pragma unroll
        for (int q = 0; q < 4; q++) acc[j][q] = 0ull;

    const float* __restrict__ Wc[4];
    bool ok[4];
    #pragma unroll
    for (int j = 0; j < 4; j++) {
        if (32 * j < N) {
            int col = 32 * j + tc;
            ok[j] = (col < N);
            Wc[j] = W + (ok[j] ? col : 0);
        }
    }
    #pragma unroll 4
    for (int k = 0; k < K; k++) {
        const float* ap = As + k * LDT + r0;
        ulonglong2 A0 = *(const ulonglong2*)(ap);
        ulonglong2 A1 = *(const ulonglong2*)(ap + 4);
        #pragma unroll
        for (int j = 0; j < 4; j++) {
            if (32 * j < N) {
                uint64_t wd = dup2(Wc[j][(size_t)k * N]);
                acc[j][0] = fma2(A0.x, wd, acc[j][0]);
                acc[j][1] = fma2(A0.y, wd, acc[j][1]);
                acc[j][2] = fma2(A1.x, wd, acc[j][2]);
                acc[j][3] = fma2(A1.y, wd, acc[j][3]);
            }
        }
    }
    #pragma unroll
    for (int j = 0; j < 4; j++) {
        if (32 * j < N) {
            int col = 32 * j + tc;
            if (ok[j]) {
                const float b = bias[col];
                float* op = Ot + col * LDT + r0;
                #pragma unroll
                for (int q = 0; q < 4; q++) {
                    float lo, hi;
                    unpack2(acc[j][q], lo, hi);
                    float v0 = lo + b, v1 = hi + b;
                    if (RELU) { v0 = fmaxf(v0, 0.f); v1 = fmaxf(v1, 0.f); }
                    op[2 * q]     = v0;
                    op[2 * q + 1] = v1;
                }
            }
        }
    }
}

// Expert output GEMM (K=64, N=8) fused with gating-weighted accumulate.
__device__ __forceinline__ void gemm_combine(const float* __restrict__ As,
                                             const float* __restrict__ W,
                                             const float* __restrict__ bias,
                                             const float* __restrict__ gate,
                                             float* __restrict__ accT,
                                             int tr, int tc)
{
    const int r0  = tr * 8;
    const int col = tc & 7;
    const int k0  = (tc >> 3) * 16;
    uint64_t acc[4] = {0ull, 0ull, 0ull, 0ull};
    const float* __restrict__ Wc = W + k0 * 8 + col;
    #pragma unroll 4
    for (int k = 0; k < 16; k++) {
        const float* ap = As + (k0 + k) * LDT + r0;
        ulonglong2 A0 = *(const ulonglong2*)(ap);
        ulonglong2 A1 = *(const ulonglong2*)(ap + 4);
        uint64_t wd = dup2(Wc[k * 8]);
        acc[0] = fma2(A0.x, wd, acc[0]);
        acc[1] = fma2(A0.y, wd, acc[1]);
        acc[2] = fma2(A1.x, wd, acc[2]);
        acc[3] = fma2(A1.y, wd, acc[3]);
    }
    #pragma unroll
    for (int q = 0; q < 4; q++) {
        double o16 = __shfl_down_sync(0xFFFFFFFFu,
                                      __longlong_as_double((long long)acc[q]), 16);
        acc[q] = add2(acc[q], (uint64_t)__double_as_longlong(o16));
        double o8 = __shfl_down_sync(0xFFFFFFFFu,
                                     __longlong_as_double((long long)acc[q]), 8);
        acc[q] = add2(acc[q], (uint64_t)__double_as_longlong(o8));
    }
    if (tc < 8) {
        const float b = bias[col];
        float* ap = accT + col * LDT + r0;
        #pragma unroll
        for (int q = 0; q < 4; q++) {
            float lo, hi;
            unpack2(acc[q], lo, hi);
            ap[2 * q]     += gate[r0 + 2 * q]     * (lo + b);
            ap[2 * q + 1] += gate[r0 + 2 * q + 1] * (hi + b);
        }
    }
}

__global__ __launch_bounds__(NTHREADS, 1)
void moe_fused_kernel(const float* __restrict__ x,
                      const float* __restrict__ ln_in_g, const float* __restrict__ ln_in_b,
                      const float* __restrict__ Wp,  const float* __restrict__ bp,
                      const float* __restrict__ Wg1, const float* __restrict__ bg1,
                      const float* __restrict__ Wg2, const float* __restrict__ bg2,
                      const float* __restrict__ Wg3, const float* __restrict__ bg3,
                      const float* __restrict__ We1, const float* __restrict__ be1,
                      const float* __restrict__ We2, const float* __restrict__ be2,
                      const float* __restrict__ We3, const float* __restrict__ be3,
                      const float* __restrict__ ln_out_g, const float* __restrict__ ln_out_b,
                      float* __restrict__ out)
{
    extern __shared__ float sm[];
    const int tid  = threadIdx.x;
    const int tr   = tid >> 5, tc = tid & 31;
    const int warp = tid >> 5, lane = tid & 31;
    const int row0 = blockIdx.x * MTILE;

    // zero the combine accumulator and A-pad rows (k=153..159 of XP and XS)
    for (int i = tid; i < SZ_ACC; i += NTHREADS) sm[OFF_ACC + i] = 0.f;
    for (int i = tid; i < (KPAD - DIN) * LDT; i += NTHREADS) {
        sm[OFF_XP + DIN * LDT + i] = 0.f;
        sm[OFF_XS + DIN * LDT + i] = 0.f;
    }

    // ---- input LayerNorm: one warp per row, write x_norm^T (tf32-rounded) ----
    {
        for (int rr = warp; rr < MTILE; rr += 16) {
            const float* xr = x + (size_t)(row0 + rr) * DIN;
            float v[5];
            float s = 0.f, ss = 0.f;
            #pragma unroll
            for (int i = 0; i < 5; i++) {
                int k = i * 32 + lane;
                float val = (k < DIN) ? xr[k] : 0.f;
                v[i] = val; s += val; ss += val * val;
            }
            #pragma unroll
            for (int o = 16; o > 0; o >>= 1) {
                s  += __shfl_xor_sync(0xFFFFFFFFu, s,  o);
                ss += __shfl_xor_sync(0xFFFFFFFFu, ss, o);
            }
            const float m   = s * (1.f / DIN);
            const float var = ss * (1.f / DIN) - m * m;
            const float inv = rsqrtf(var + EPS);
            #pragma unroll
            for (int i = 0; i < 5; i++) {
                int k = i * 32 + lane;
                if (k < DIN)
                    sm[OFF_XS + k * LDT + rr] =
                        tf32r((v[i] - m) * inv * ln_in_g[k] + ln_in_b[k]);
            }
        }
    }
    __syncthreads();

    // ---- x_proj = relu(x_norm @ Wp + bp) + x_norm  (tensor, tf32 out) ----
    mma_gemmT<DIN, DIN, true, true, true>(sm + OFF_XS, Wp, bp, sm + OFF_XP, warp, lane);
    __syncthreads();

    // ---- gating MLP (scalar fp32) ----
    gemmT<DIN, GH_, true>(sm + OFF_XP, Wg1, bg1, sm + OFF_XS, tr, tc);
    __syncthreads();
    gemmT<GH_, GH2_, true>(sm + OFF_XS, Wg2, bg2, sm + OFF_G2, tr, tc);
    __syncthreads();
    gemmT<GH2_, 8, false>(sm + OFF_G2, Wg3, bg3, sm + OFF_GATE, tr, tc);
    __syncthreads();

    // ---- softmax over experts, write gating output ----
    if (tid < MTILE) {
        float l[8];
        float mx = -INFINITY;
        #pragma unroll
        for (int e = 0; e < NE; e++) { l[e] = sm[OFF_GATE + e * LDT + tid]; mx = fmaxf(mx, l[e]); }
        float s = 0.f;
        #pragma unroll
        for (int e = 0; e < NE; e++) { l[e] = expf(l[e] - mx); s += l[e]; }
        const float invs = 1.f / s;
        float* gw = out + (size_t)B_ * 8 + (size_t)(row0 + tid) * 8;
        #pragma unroll
        for (int e = 0; e < NE; e++) {
            float g = l[e] * invs;
            sm[OFF_GATE + e * LDT + tid] = g;
            gw[e] = g;
        }
    }
    __syncthreads();

    // ---- experts: sequential, tensor GEMMs + scalar combine ----
    for (int e = 0; e < NE; e++) {
        mma_gemmT<DIN, H1_, true, false, true>(sm + OFF_XP, We1 + (size_t)e * DIN * H1_,
                                               be1 + e * H1_, sm + OFF_XS, warp, lane);
        __syncthreads();
        mma_gemmT<H1_, H2_, true, false, false>(sm + OFF_XS, We2 + (size_t)e * H1_ * H2_,
                                                be2 + e * H2_, sm + OFF_H2, warp, lane);
        __syncthreads();
        gemm_combine(sm + OFF_H2, We3 + (size_t)e * H2_ * DOUT, be3 + e * DOUT,
                     sm + OFF_GATE + e * LDT, sm + OFF_ACC, tr, tc);
        // no barrier needed: combine reads H2/GATE, writes ACC; next We1 writes XS
        // only, and the barrier after it orders everything else.
    }
    __syncthreads();

    // ---- output LayerNorm over 8 dims, write out ----
    if (tid < MTILE) {
        float y[8];
        float s = 0.f;
        #pragma unroll
        for (int e = 0; e < DOUT; e++) { y[e] = sm[OFF_ACC + e * LDT + tid]; s += y[e]; }
        const float m = s * 0.125f;
        float var = 0.f;
        #pragma unroll
        for (int e = 0; e < DOUT; e++) { float d = y[e] - m; var += d * d; }
        var *= 0.125f;
        const float inv = rsqrtf(var + EPS);
        float* op = out + (size_t)(row0 + tid) * 8;
        #pragma unroll
        for (int e = 0; e < DOUT; e++)
            op[e] = (y[e] - m) * inv * ln_out_g[e] + ln_out_b[e];
    }
}

extern "C" void kernel_launch(void* const* d_in, const int* in_sizes, int n_in,
                              void* d_out, int out_size)
{
    const float* x       = (const float*)d_in[0];
    const float* ln_in_g = (const float*)d_in[1];
    const float* ln_in_b = (const float*)d_in[2];
    const float* Wp      = (const float*)d_in[3];
    const float* bp      = (const float*)d_in[4];
    const float* Wg1     = (const float*)d_in[5];
    const float* bg1     = (const float*)d_in[6];
    const float* Wg2     = (const float*)d_in[7];
    const float* bg2     = (const float*)d_in[8];
    const float* Wg3     = (const float*)d_in[9];
    const float* bg3     = (const float*)d_in[10];
    const float* We1     = (const float*)d_in[11];
    const float* be1     = (const float*)d_in[12];
    const float* We2     = (const float*)d_in[13];
    const float* be2     = (const float*)d_in[14];
    const float* We3     = (const float*)d_in[15];
    const float* be3     = (const float*)d_in[16];
    const float* ln_out_g= (const float*)d_in[17];
    const float* ln_out_b= (const float*)d_in[18];
    float* out = (float*)d_out;

    const size_t smem = SMEM_FLOATS * sizeof(float);
    cudaFuncSetAttribute(moe_fused_kernel,
                         cudaFuncAttributeMaxDynamicSharedMemorySize, (int)smem);

    moe_fused_kernel<<<B_ / MTILE, NTHREADS, smem>>>(
        x, ln_in_g, ln_in_b, Wp, bp, Wg1, bg1, Wg2, bg2, Wg3, bg3,
        We1, be1, We2, be2, We3, be3, ln_out_g, ln_out_b, out);
}